// round 3
// baseline (speedup 1.0000x reference)
#include <cuda_runtime.h>
#include <math.h>

// Problem dims
#define BB 64
#define CC 256
#define HWN 1024
#define SS 512
#define DD 256
#define TAUV 0.07f
#define SIGMA (1.0f/1024.0f)

// GEMM tiling
#define BMM 128
#define BNN 128
#define BKK 8
#define LDS_ 132   // padded smem row stride (floats)

// ---------------- scratch (static device globals; no allocation) ----------------
__device__ float g_patches[(size_t)BB*HWN*DD];   // 64 MB  [b][p][d]
__device__ float g_tokens [(size_t)BB*SS*DD];    // 32 MB  [b][s][d]
__device__ float g_sim    [(size_t)BB*HWN*SS];   // 128 MB [b][p][s]
__device__ float g_lgve   [(size_t)BB*SS*DD];    // 32 MB
__device__ float g_lnv    [(size_t)BB*SS*DD];    // 32 MB
__device__ float g_lnt    [(size_t)BB*SS*DD];    // 32 MB
__device__ float g_fsim   [(size_t)BB*SS*SS];    // 64 MB  [b][i][j]
__device__ float g_partV[BB*8*DD];
__device__ float g_partT[BB*4*DD];
__device__ float g_gimg[BB*DD];
__device__ float g_gtxt[BB*DD];
__device__ float g_norms[128];
__device__ float g_gsim[64*64];
__device__ float g_mn  [BB*SS];
__device__ float g_rinv[BB*SS];
__device__ float g_zinv[BB*SS];
__device__ float g_rowterm[BB*SS];
__device__ float g_colterm[BB*SS];
__device__ float g_gloss;

// ---------------- f32x2 helpers ----------------
__device__ __forceinline__ unsigned long long fma2(unsigned long long a,
                                                   unsigned long long b,
                                                   unsigned long long c) {
    unsigned long long d;
    asm("fma.rn.f32x2 %0, %1, %2, %3;" : "=l"(d) : "l"(a), "l"(b), "l"(c));
    return d;
}
__device__ __forceinline__ unsigned long long dup2(float x) {
    unsigned long long d;
    asm("mov.b64 %0, {%1, %2};" : "=l"(d) : "f"(x), "f"(x));
    return d;
}
__device__ __forceinline__ void unpack2(unsigned long long v, float& lo, float& hi) {
    asm("mov.b64 {%0, %1}, %2;" : "=f"(lo), "=f"(hi) : "l"(v));
}

// ---------------- GEMM compute core: one BK=8 slab ----------------
__device__ __forceinline__ void tile_compute(const float* As, const float* Bs,
                                             int tx, int ty,
                                             unsigned long long acc[8][4]) {
#pragma unroll
    for (int kk = 0; kk < BKK; kk++) {
        const ulonglong2* bp = (const ulonglong2*)(Bs + kk*LDS_ + tx*8);
        ulonglong2 q0 = bp[0], q1 = bp[1];
        unsigned long long b0 = q0.x, b1 = q0.y, b2 = q1.x, b3 = q1.y;
        const float* ap = As + kk*LDS_ + ty*8;
        float4 a0 = *(const float4*)ap;
        float4 a1 = *(const float4*)(ap + 4);
        float av[8] = {a0.x,a0.y,a0.z,a0.w,a1.x,a1.y,a1.z,a1.w};
#pragma unroll
        for (int i = 0; i < 8; i++) {
            unsigned long long ad = dup2(av[i]);
            acc[i][0] = fma2(ad, b0, acc[i][0]);
            acc[i][1] = fma2(ad, b1, acc[i][1]);
            acc[i][2] = fma2(ad, b2, acc[i][2]);
            acc[i][3] = fma2(ad, b3, acc[i][3]);
        }
    }
}

// AM: 0 = A row-major [m][k] (transpose into As)
//     1 = A direct    [k][m] (m contiguous)
//     2 = A direct + weight transform (lgve)
// BMODE: 0 = B row-major [n][k] (transpose), 1 = B direct [k][n]
// EP: 0 plain, 1 +bias, 2 *cscale
template<int AM, int BMODE, int EP>
__device__ __forceinline__ void gemm_core(
    const float* __restrict__ A, const float* __restrict__ B, float* __restrict__ C,
    int K, int lda, int ldb, int ldc,
    size_t strA, size_t strB, size_t strC,
    const float* __restrict__ bias, float cscale)
{
    __shared__ float As[2][BKK*LDS_];
    __shared__ float Bs[2][BKK*LDS_];
    int b = blockIdx.z;
    A += (size_t)b * strA; B += (size_t)b * strB; C += (size_t)b * strC;
    int m0 = blockIdx.x * BMM, n0 = blockIdx.y * BNN;
    int t = threadIdx.x, tx = t & 15, ty = t >> 4;

    int kD = t >> 5, xD4 = (t & 31) * 4;   // direct-load mapping
    int mT = t >> 1, kT4 = (t & 1) * 4;    // transpose-load mapping

    float4 wmn, wri, wzi;
    if (AM == 2) {
        wmn = *(const float4*)&g_mn  [b*SS + m0 + xD4];
        wri = *(const float4*)&g_rinv[b*SS + m0 + xD4];
        wzi = *(const float4*)&g_zinv[b*SS + m0 + xD4];
    }

    unsigned long long acc[8][4];
    unsigned long long z = dup2(0.f);
#pragma unroll
    for (int i = 0; i < 8; i++)
#pragma unroll
        for (int j = 0; j < 4; j++) acc[i][j] = z;

    const int KT = K / BKK;

    // --- loaders ---
    auto ldgA = [&](int kt) -> float4 {
        if (AM == 0) return *(const float4*)&A[(size_t)(m0 + mT) * lda + kt*BKK + kT4];
        else         return *(const float4*)&A[(size_t)(kt*BKK + kD) * lda + m0 + xD4];
    };
    auto ldgB = [&](int kt) -> float4 {
        if (BMODE == 0) return *(const float4*)&B[(size_t)(n0 + mT) * ldb + kt*BKK + kT4];
        else            return *(const float4*)&B[(size_t)(kt*BKK + kD) * ldb + n0 + xD4];
    };
    auto xform = [&](float v, float mn, float ri, float zi) -> float {
        float tv = (v - mn) * ri;
        tv = (tv < SIGMA) ? 0.f : tv;
        return tv * zi;
    };
    auto stsA = [&](float* buf, float4 v) {
        if (AM == 0) {
            buf[(kT4+0)*LDS_ + mT] = v.x;
            buf[(kT4+1)*LDS_ + mT] = v.y;
            buf[(kT4+2)*LDS_ + mT] = v.z;
            buf[(kT4+3)*LDS_ + mT] = v.w;
        } else {
            if (AM == 2) {
                v.x = xform(v.x, wmn.x, wri.x, wzi.x);
                v.y = xform(v.y, wmn.y, wri.y, wzi.y);
                v.z = xform(v.z, wmn.z, wri.z, wzi.z);
                v.w = xform(v.w, wmn.w, wri.w, wzi.w);
            }
            *(float4*)&buf[kD*LDS_ + xD4] = v;
        }
    };
    auto stsB = [&](float* buf, float4 v) {
        if (BMODE == 0) {
            buf[(kT4+0)*LDS_ + mT] = v.x;
            buf[(kT4+1)*LDS_ + mT] = v.y;
            buf[(kT4+2)*LDS_ + mT] = v.z;
            buf[(kT4+3)*LDS_ + mT] = v.w;
        } else {
            *(float4*)&buf[kD*LDS_ + xD4] = v;
        }
    };

    // prologue
    float4 ra = ldgA(0), rb = ldgB(0);
    stsA(As[0], ra); stsB(Bs[0], rb);
    __syncthreads();

    int cur = 0;
    for (int kt = 0; kt < KT; kt++) {
        if (kt + 1 < KT) { ra = ldgA(kt + 1); rb = ldgB(kt + 1); }
        tile_compute(As[cur], Bs[cur], tx, ty, acc);
        if (kt + 1 < KT) {
            stsA(As[cur ^ 1], ra); stsB(Bs[cur ^ 1], rb);
            __syncthreads();
        }
        cur ^= 1;
    }

    // epilogue
#pragma unroll
    for (int i = 0; i < 8; i++) {
        float r[8];
        unpack2(acc[i][0], r[0], r[1]);
        unpack2(acc[i][1], r[2], r[3]);
        unpack2(acc[i][2], r[4], r[5]);
        unpack2(acc[i][3], r[6], r[7]);
        if (EP == 1) {
            float4 bq0 = *(const float4*)&bias[n0 + tx*8];
            float4 bq1 = *(const float4*)&bias[n0 + tx*8 + 4];
            r[0]+=bq0.x; r[1]+=bq0.y; r[2]+=bq0.z; r[3]+=bq0.w;
            r[4]+=bq1.x; r[5]+=bq1.y; r[6]+=bq1.z; r[7]+=bq1.w;
        }
        if (EP == 2) {
#pragma unroll
            for (int j = 0; j < 8; j++) r[j] *= cscale;
        }
        float* cp = &C[(size_t)(m0 + ty*8 + i) * ldc + n0 + tx*8];
        *(float4*)cp       = make_float4(r[0], r[1], r[2], r[3]);
        *(float4*)(cp + 4) = make_float4(r[4], r[5], r[6], r[7]);
    }
}

// ---------------- GEMM wrappers ----------------
__global__ __launch_bounds__(256,2) void k_patch(const float* __restrict__ img,
                                                 const float* __restrict__ Wv,
                                                 const float* __restrict__ bv) {
    // A[k=c][m=p] = img[b][c][p] direct; B = Wv row-major
    gemm_core<1,0,1>(img, Wv, g_patches, CC, HWN, DD, DD,
                     (size_t)CC*HWN, 0, (size_t)HWN*DD, bv, 1.f);
}
__global__ __launch_bounds__(256,2) void k_tok(const float* __restrict__ txt,
                                               const float* __restrict__ Wt,
                                               const float* __restrict__ bt) {
    gemm_core<0,0,1>(txt, Wt, g_tokens, DD, DD, DD, DD,
                     (size_t)SS*DD, 0, (size_t)SS*DD, bt, 1.f);
}
__global__ __launch_bounds__(256,2) void k_sim() {
    gemm_core<0,0,0>(g_patches, g_tokens, g_sim, DD, DD, DD, SS,
                     (size_t)HWN*DD, (size_t)SS*DD, (size_t)HWN*SS, nullptr, 1.f);
}
__global__ __launch_bounds__(256,2) void k_lgve() {
    // A[k=p][m=s] = weights from g_sim (transform in loader); B[k=p][n=d] = patches direct
    gemm_core<2,1,0>(g_sim, g_patches, g_lgve, HWN, SS, DD, DD,
                     (size_t)HWN*SS, (size_t)HWN*DD, (size_t)SS*DD, nullptr, 1.f);
}
__global__ __launch_bounds__(256,2) void k_fsim() {
    gemm_core<0,0,2>(g_lnv, g_lnt, g_fsim, DD, DD, DD, SS,
                     (size_t)SS*DD, (size_t)SS*DD, (size_t)SS*SS, nullptr, 1.0f/TAUV);
}

// ---------------- column stats: min/max over p, then Z ----------------
__global__ void k_colstats() {
    int b = blockIdx.y;
    int tx = threadIdx.x, ty = threadIdx.y;
    int s = blockIdx.x * 32 + tx;
    const float* simb = g_sim + (size_t)b * HWN * SS;

    __shared__ float red0[8][32], red1[8][32];
    __shared__ float s_mn[32], s_rinv[32];

    float vmn = 1e30f, vmx = -1e30f;
    for (int p = ty; p < HWN; p += 8) {
        float v = simb[(size_t)p * SS + s];
        vmn = fminf(vmn, v);
        vmx = fmaxf(vmx, v);
    }
    red0[ty][tx] = vmn; red1[ty][tx] = vmx;
    __syncthreads();
    if (ty == 0) {
        float mn = red0[0][tx], mx = red1[0][tx];
#pragma unroll
        for (int q = 1; q < 8; q++) {
            mn = fminf(mn, red0[q][tx]);
            mx = fmaxf(mx, red1[q][tx]);
        }
        float rinv = 1.0f / (mx - mn + 1e-8f);
        s_mn[tx] = mn; s_rinv[tx] = rinv;
        g_mn[b*SS + s] = mn;
        g_rinv[b*SS + s] = rinv;
    }
    __syncthreads();
    float mn = s_mn[tx], rinv = s_rinv[tx];
    float zsum = 0.f;
    for (int p = ty; p < HWN; p += 8) {
        float v = simb[(size_t)p * SS + s];
        float tv = (v - mn) * rinv;
        if (tv >= SIGMA) zsum += tv;
    }
    red0[ty][tx] = zsum;
    __syncthreads();
    if (ty == 0) {
        float Z = red0[0][tx];
#pragma unroll
        for (int q = 1; q < 8; q++) Z += red0[q][tx];
        g_zinv[b*SS + s] = 1.0f / fmaxf(Z, 1e-12f);
    }
}

// ---------------- row L2 normalize ----------------
__global__ void k_l2norm(int which) {
    const float* in  = which ? g_tokens : g_lgve;
    float*       out = which ? g_lnt    : g_lnv;
    int warp = threadIdx.x >> 5, lane = threadIdx.x & 31;
    size_t r = (size_t)blockIdx.x * 8 + warp;
    const float* row = in + r * DD;
    float v[8];
    float s = 0.f;
#pragma unroll
    for (int q = 0; q < 8; q++) { v[q] = row[lane + q*32]; s += v[q]*v[q]; }
#pragma unroll
    for (int off = 16; off > 0; off >>= 1) s += __shfl_xor_sync(0xffffffffu, s, off);
    float inv = 1.0f / fmaxf(sqrtf(s), 1e-8f);
#pragma unroll
    for (int q = 0; q < 8; q++) out[r * DD + lane + q*32] = v[q] * inv;
}

// ---------------- mean-pool partials ----------------
__global__ void k_meanp() {
    int ch = blockIdx.x, b = blockIdx.y, d = threadIdx.x;
    const float* base = g_patches + (size_t)b * HWN * DD;
    float s = 0.f;
    for (int p = ch*128; p < ch*128 + 128; p++) s += base[(size_t)p * DD + d];
    g_partV[(b*8 + ch)*DD + d] = s;
}
__global__ void k_meant() {
    int ch = blockIdx.x, b = blockIdx.y, d = threadIdx.x;
    const float* base = g_tokens + (size_t)b * SS * DD;
    float s = 0.f;
    for (int p = ch*128; p < ch*128 + 128; p++) s += base[(size_t)p * DD + d];
    g_partT[(b*4 + ch)*DD + d] = s;
}

// ---------------- global adapters on pooled means ----------------
__global__ void k_gimg(const float* __restrict__ Wv, const float* __restrict__ bv) {
    __shared__ float sm[DD];
    int b = blockIdx.x, d = threadIdx.x;
    float s = 0.f;
#pragma unroll
    for (int ch = 0; ch < 8; ch++) s += g_partV[(b*8 + ch)*DD + d];
    sm[d] = s * (1.0f / (float)HWN);
    __syncthreads();
    const float4* wr = (const float4*)&Wv[(size_t)d * DD];
    float a0 = bv[d], a1 = 0.f, a2 = 0.f, a3 = 0.f;
#pragma unroll
    for (int c = 0; c < DD/4; c++) {
        float4 w = wr[c];
        a0 = fmaf(sm[4*c+0], w.x, a0);
        a1 = fmaf(sm[4*c+1], w.y, a1);
        a2 = fmaf(sm[4*c+2], w.z, a2);
        a3 = fmaf(sm[4*c+3], w.w, a3);
    }
    g_gimg[b*DD + d] = (a0 + a1) + (a2 + a3);
}
__global__ void k_gtxt(const float* __restrict__ Wt, const float* __restrict__ bt) {
    __shared__ float sm[DD];
    int b = blockIdx.x, d = threadIdx.x;
    float s = 0.f;
#pragma unroll
    for (int ch = 0; ch < 4; ch++) s += g_partT[(b*4 + ch)*DD + d];
    sm[d] = s * (1.0f / (float)SS);
    __syncthreads();
    const float4* wr = (const float4*)&Wt[(size_t)d * DD];
    float a0 = bt[d], a1 = 0.f, a2 = 0.f, a3 = 0.f;
#pragma unroll
    for (int c = 0; c < DD/4; c++) {
        float4 w = wr[c];
        a0 = fmaf(sm[4*c+0], w.x, a0);
        a1 = fmaf(sm[4*c+1], w.y, a1);
        a2 = fmaf(sm[4*c+2], w.z, a2);
        a3 = fmaf(sm[4*c+3], w.w, a3);
    }
    g_gtxt[b*DD + d] = (a0 + a1) + (a2 + a3);
}

// ---------------- global embedding norms ----------------
__global__ void k_gnorm() {
    int r = blockIdx.x, lane = threadIdx.x;
    const float* row = (r < 64) ? (g_gimg + (size_t)r * DD)
                                : (g_gtxt + (size_t)(r - 64) * DD);
    float s = 0.f;
#pragma unroll
    for (int q = 0; q < 8; q++) { float v = row[lane + q*32]; s += v*v; }
#pragma unroll
    for (int off = 16; off > 0; off >>= 1) s += __shfl_xor_sync(0xffffffffu, s, off);
    if (lane == 0) g_norms[r] = fmaxf(sqrtf(s), 1e-8f);
}

// ---------------- global sim matrix 64x64 ----------------
__global__ void k_gsim() {
    __shared__ float srow[DD];
    int i = blockIdx.x;
    int warp = threadIdx.x >> 5, lane = threadIdx.x & 31;
    for (int c = threadIdx.x; c < DD; c += 256) srow[c] = g_gimg[(size_t)i * DD + c];
    __syncthreads();
    float ni = g_norms[i];
    for (int j = warp; j < 64; j += 8) {
        const float* trow = g_gtxt + (size_t)j * DD;
        float s = 0.f;
#pragma unroll
        for (int q = 0; q < 8; q++) s += srow[lane + q*32] * trow[lane + q*32];
#pragma unroll
        for (int off = 16; off > 0; off >>= 1) s += __shfl_xor_sync(0xffffffffu, s, off);
        if (lane == 0)
            g_gsim[i*64 + j] = s / (ni * g_norms[64 + j]) * (1.0f / TAUV);
    }
}

// ---------------- global loss ----------------
__global__ void k_gloss() {
    __shared__ float sim[64][65];
    __shared__ float r1[64], r2[64];
    int t = threadIdx.x;  // 64 threads
    for (int idx = t; idx < 4096; idx += 64) sim[idx >> 6][idx & 63] = g_gsim[idx];
    __syncthreads();
    float m = -1e30f;
    for (int j = 0; j < 64; j++) m = fmaxf(m, sim[t][j]);
    float s = 0.f;
    for (int j = 0; j < 64; j++) s += expf(sim[t][j] - m);
    r1[t] = m + logf(s) - sim[t][t];
    m = -1e30f;
    for (int i = 0; i < 64; i++) m = fmaxf(m, sim[i][t]);
    s = 0.f;
    for (int i = 0; i < 64; i++) s += expf(sim[i][t] - m);
    r2[t] = m + logf(s) - sim[t][t];
    __syncthreads();
    if (t == 0) {
        float acc = 0.f;
        for (int r = 0; r < 64; r++) acc += r1[r] + r2[r];
        g_gloss = 0.5f * acc / 64.0f;
    }
}

// ---------------- fsim row / col LSE terms ----------------
__global__ void k_frow() {
    int warp = threadIdx.x >> 5, lane = threadIdx.x & 31;
    int r = blockIdx.x * 8 + warp;
    int b = r >> 9, i = r & (SS - 1);
    const float* row = g_fsim + ((size_t)b * SS + i) * SS;
    float v[16];
#pragma unroll
    for (int q = 0; q < 16; q++) v[q] = row[lane + q*32];
    float m = -1e30f;
#pragma unroll
    for (int q = 0; q < 16; q++) m = fmaxf(m, v[q]);
#pragma unroll
    for (int off = 16; off > 0; off >>= 1) m = fmaxf(m, __shfl_xor_sync(0xffffffffu, m, off));
    float s = 0.f;
#pragma unroll
    for (int q = 0; q < 16; q++) s += expf(v[q] - m);
#pragma unroll
    for (int off = 16; off > 0; off >>= 1) s += __shfl_xor_sync(0xffffffffu, s, off);
    if (lane == 0) g_rowterm[r] = m + logf(s) - row[i];
}

__global__ void k_fcol() {
    int b = blockIdx.y;
    int tx = threadIdx.x, ty = threadIdx.y;
    int j = blockIdx.x * 32 + tx;
    const float* Fb = g_fsim + (size_t)b * SS * SS;
    float m = -1e30f, s = 0.f;
    for (int i = ty; i < SS; i += 8) {
        float x = Fb[(size_t)i * SS + j];
        float nm = fmaxf(m, x);
        s = s * expf(m - nm) + expf(x - nm);
        m = nm;
    }
    __shared__ float sm[8][32], sv[8][32];
    sm[ty][tx] = m; sv[ty][tx] = s;
    __syncthreads();
    if (ty == 0) {
        float M = sm[0][tx], Sv = sv[0][tx];
#pragma unroll
        for (int q = 1; q < 8; q++) {
            float m2 = sm[q][tx], s2 = sv[q][tx];
            float nm = fmaxf(M, m2);
            Sv = Sv * expf(M - nm) + s2 * expf(m2 - nm);
            M = nm;
        }
        g_colterm[b*SS + j] = M + logf(Sv) - Fb[(size_t)j * SS + j];
    }
}

// ---------------- final scalar ----------------
__global__ void k_final(float* out) {
    __shared__ float red[256];
    int t = threadIdx.x;
    float s = 0.f;
    for (int idx = t; idx < BB*SS; idx += 256) s += g_rowterm[idx] + g_colterm[idx];
    red[t] = s;
    __syncthreads();
    for (int o = 128; o > 0; o >>= 1) {
        if (t < o) red[t] += red[t + o];
        __syncthreads();
    }
    if (t == 0) out[0] = g_gloss + 0.5f * red[0] / (float)(BB*SS);
}

// ---------------- launch ----------------
extern "C" void kernel_launch(void* const* d_in, const int* in_sizes, int n_in,
                              void* d_out, int out_size) {
    const float* img = (const float*)d_in[0];
    const float* txt = (const float*)d_in[1];
    const float* Wv  = (const float*)d_in[2];
    const float* bv  = (const float*)d_in[3];
    const float* Wt  = (const float*)d_in[4];
    const float* bt  = (const float*)d_in[5];
    float* out = (float*)d_out;

    // Launch order arranged so the heavy k_sim GEMM sits at position 6
    // (ncu -s 5 -c 1 captures it next profile).
    k_patch<<<dim3(HWN/BMM, DD/BNN, BB), 256>>>(img, Wv, bv);   // 1
    k_tok  <<<dim3(SS/BMM,  DD/BNN, BB), 256>>>(txt, Wt, bt);   // 2
    k_meanp<<<dim3(8, BB), 256>>>();                            // 3
    k_meant<<<dim3(4, BB), 256>>>();                            // 4
    k_gimg <<<BB, 256>>>(Wv, bv);                               // 5
    k_sim  <<<dim3(HWN/BMM, SS/BNN, BB), 256>>>();              // 6  <- profiled
    k_gtxt <<<BB, 256>>>(Wt, bt);                               // 7
    k_gnorm<<<128, 32>>>();                                     // 8
    k_gsim <<<64, 256>>>();                                     // 9
    k_gloss<<<1, 64>>>();                                       // 10

    k_colstats<<<dim3(SS/32, BB), dim3(32, 8)>>>();
    k_lgve <<<dim3(SS/BMM, DD/BNN, BB), 256>>>();
    k_l2norm<<<(BB*SS)/8, 256>>>(0);  // lgve -> lnv
    k_l2norm<<<(BB*SS)/8, 256>>>(1);  // tokens -> lnt
    k_fsim <<<dim3(SS/BMM, SS/BNN, BB), 256>>>();
    k_frow <<<(BB*SS)/8, 256>>>();
    k_fcol <<<dim3(SS/32, BB), dim3(32, 8)>>>();
    k_final<<<1, 256>>>(out);
}

// round 7
// speedup vs baseline: 2.9374x; 2.9374x over previous
#include <cuda_runtime.h>
#include <cuda_bf16.h>
#include <math.h>
#include <stdint.h>

// Problem dims
#define BB 64
#define CC 256
#define HWN 1024
#define SS 512
#define DD 256
#define TAUV 0.07f
#define SIGMA (1.0f/1024.0f)

// ---------------- scratch (static device globals; no allocation) ----------------
__device__ float g_patches[(size_t)BB*HWN*DD];   // 64 MB  [b][p][d]
__device__ float g_tokens [(size_t)BB*SS*DD];    // 32 MB  [b][s][d]
__device__ float g_sim    [(size_t)BB*HWN*SS];   // 128 MB [b][p][s]
__device__ float g_lgve   [(size_t)BB*SS*DD];    // 32 MB
__device__ float g_lnv    [(size_t)BB*SS*DD];    // 32 MB
__device__ float g_lnt    [(size_t)BB*SS*DD];    // 32 MB
__device__ float g_fsim   [(size_t)BB*SS*SS];    // 64 MB  [b][i][j]
__device__ float g_partV[BB*8*DD];
__device__ float g_partT[BB*4*DD];
__device__ float g_gimg[BB*DD];
__device__ float g_gtxt[BB*DD];
__device__ float g_norms[128];
__device__ float g_gsim[64*64];
__device__ float g_mn  [BB*SS];
__device__ float g_rinv[BB*SS];
__device__ float g_zinv[BB*SS];
__device__ float g_rowterm[BB*SS];
__device__ float g_colterm[BB*SS];
__device__ float g_gloss;

// ---------------- helpers ----------------
// bf16 hi/lo split of a pair -> packed bf16x2 words (x0 in low half)
__device__ __forceinline__ void split_pair(float x0, float x1, uint32_t& h, uint32_t& l) {
    asm("cvt.rn.bf16x2.f32 %0, %1, %2;" : "=r"(h) : "f"(x1), "f"(x0));
    float f0 = __uint_as_float(h << 16);           // bf16(x0)
    float f1 = __uint_as_float(h & 0xffff0000u);   // bf16(x1)
    asm("cvt.rn.bf16x2.f32 %0, %1, %2;" : "=r"(l) : "f"(x1 - f1), "f"(x0 - f0));
}

__device__ __forceinline__ void mma16816(float* c, const uint32_t* a, const uint32_t* b2) {
    asm volatile(
        "mma.sync.aligned.m16n8k16.row.col.f32.bf16.bf16.f32 "
        "{%0,%1,%2,%3},{%4,%5,%6,%7},{%8,%9},{%0,%1,%2,%3};"
        : "+f"(c[0]), "+f"(c[1]), "+f"(c[2]), "+f"(c[3])
        : "r"(a[0]), "r"(a[1]), "r"(a[2]), "r"(a[3]), "r"(b2[0]), "r"(b2[1]));
}

// SMEM layout (dynamic):
//   [0,512)       bias
//   [512, +16K)   A buf0   (128 rows x 128B: [hi 64B | lo 64B], SW128-swizzled)
//   [+16K, +32K)  A buf1
//   [+32K, +48K)  B buf0
//   [+48K, +64K)  B buf1
#define OFF_AB   512
#define TILEB    16384
#define SMEMSZ   (512 + 4*16384)

// ================= HMMA GEMM: C[M,N] = A·B^T per batch =================
// AMODE: 0 = A[m][k] row-major; 1 = A[k][m] (m contiguous); 2 = mode1 + lgve weight xform
// BMODE: 0 = B[n][k] row-major; 1 = B[k][n] (n contiguous)
// EP:    0 plain; 1 +bias[n]; 2 *scale
template<int AMODE, int BMODE, int EP>
__device__ __forceinline__ void tc_gemm(
    const float* __restrict__ A, const float* __restrict__ B, float* __restrict__ C,
    int K, int lda, int ldb, int ldc, size_t sA, size_t sB, size_t sC,
    const float* __restrict__ bias, float scale)
{
    extern __shared__ char smem[];
    float* sbias = (float*)smem;
    char* bufA0 = smem + OFF_AB;
    char* bufB0 = smem + OFF_AB + 2*TILEB;

    int tid = threadIdx.x, lane = tid & 31, wid = tid >> 5;
    int g = lane >> 2, tg = lane & 3;
    int wm = wid & 1, wn = wid >> 1;       // 2 x 4 warp grid; warp tile 64x32
    int b = blockIdx.z;
    int m0 = blockIdx.x * 128, n0 = blockIdx.y * 128;

    const float* Abase = (AMODE == 0) ? (A + (size_t)b*sA + (size_t)m0*lda)
                                      : (A + (size_t)b*sA + m0);
    const float* Bbase = (BMODE == 0) ? (B + (size_t)b*sB + (size_t)n0*ldb)
                                      : (B + (size_t)b*sB + n0);
    float* Cb = C + (size_t)b*sC;

    if (EP == 1 && tid < 128) sbias[tid] = bias[n0 + tid];

    // staging maps
    const int aRow = (AMODE == 0) ? (tid >> 1) : (tid & 127);
    const int aSeg = (AMODE == 0) ? ((tid & 1) * 16) : ((tid >> 7) * 16);
    const int bRow = (BMODE == 0) ? (tid >> 1) : (tid & 127);
    const int bSeg = (BMODE == 0) ? ((tid & 1) * 16) : ((tid >> 7) * 16);

    float xmn = 0.f, xri = 0.f, xzi = 0.f;
    if (AMODE == 2) {
        xmn = g_mn  [b*SS + m0 + aRow];
        xri = g_rinv[b*SS + m0 + aRow];
        xzi = g_zinv[b*SS + m0 + aRow];
    }

    float acc[4][4][4];
#pragma unroll
    for (int i = 0; i < 4; i++)
#pragma unroll
        for (int j = 0; j < 4; j++)
#pragma unroll
            for (int q = 0; q < 4; q++) acc[i][j][q] = 0.f;

    auto ldgA = [&](int c, float* v) {
        if (AMODE == 0) {
            const float* p = Abase + (size_t)aRow * lda + c*32 + aSeg;
            *(float4*)(v+0)  = *(const float4*)(p+0);
            *(float4*)(v+4)  = *(const float4*)(p+4);
            *(float4*)(v+8)  = *(const float4*)(p+8);
            *(float4*)(v+12) = *(const float4*)(p+12);
        } else {
            const float* p = Abase + (size_t)(c*32 + aSeg) * lda + aRow;
#pragma unroll
            for (int q = 0; q < 16; q++) v[q] = p[(size_t)q * lda];
        }
    };
    auto ldgB = [&](int c, float* v) {
        if (BMODE == 0) {
            const float* p = Bbase + (size_t)bRow * ldb + c*32 + bSeg;
            *(float4*)(v+0)  = *(const float4*)(p+0);
            *(float4*)(v+4)  = *(const float4*)(p+4);
            *(float4*)(v+8)  = *(const float4*)(p+8);
            *(float4*)(v+12) = *(const float4*)(p+12);
        } else {
            const float* p = Bbase + (size_t)(c*32 + bSeg) * ldb + bRow;
#pragma unroll
            for (int q = 0; q < 16; q++) v[q] = p[(size_t)q * ldb];
        }
    };
    auto stsA = [&](int buf, float* v) {
        if (AMODE == 2) {
#pragma unroll
            for (int q = 0; q < 16; q++) {
                float t = (v[q] - xmn) * xri;
                t = (t < SIGMA) ? 0.f : t;
                v[q] = t * xzi;
            }
        }
        uint32_t h[8], l[8];
#pragma unroll
        for (int q = 0; q < 8; q++) split_pair(v[2*q], v[2*q+1], h[q], l[q]);
        char* dst = bufA0 + buf*TILEB + aRow*128;
        int mask = (aRow & 7) << 4, cb = aSeg * 2;
        *(uint4*)(dst + ((cb     ) ^ mask)) = make_uint4(h[0], h[1], h[2], h[3]);
        *(uint4*)(dst + ((cb + 16) ^ mask)) = make_uint4(h[4], h[5], h[6], h[7]);
        *(uint4*)(dst + ((cb + 64) ^ mask)) = make_uint4(l[0], l[1], l[2], l[3]);
        *(uint4*)(dst + ((cb + 80) ^ mask)) = make_uint4(l[4], l[5], l[6], l[7]);
    };
    auto stsB = [&](int buf, float* v) {
        uint32_t h[8], l[8];
#pragma unroll
        for (int q = 0; q < 8; q++) split_pair(v[2*q], v[2*q+1], h[q], l[q]);
        char* dst = bufB0 + buf*TILEB + bRow*128;
        int mask = (bRow & 7) << 4, cb = bSeg * 2;
        *(uint4*)(dst + ((cb     ) ^ mask)) = make_uint4(h[0], h[1], h[2], h[3]);
        *(uint4*)(dst + ((cb + 16) ^ mask)) = make_uint4(h[4], h[5], h[6], h[7]);
        *(uint4*)(dst + ((cb + 64) ^ mask)) = make_uint4(l[0], l[1], l[2], l[3]);
        *(uint4*)(dst + ((cb + 80) ^ mask)) = make_uint4(l[4], l[5], l[6], l[7]);
    };

    float va[16], vb[16];
    ldgA(0, va); ldgB(0, vb);
    stsA(0, va); stsB(0, vb);
    __syncthreads();

    const int nch = K / 32;
    const int mask = g << 4;
    for (int c = 0; c < nch; c++) {
        if (c + 1 < nch) { ldgA(c + 1, va); ldgB(c + 1, vb); }
        const char* a = bufA0 + (c & 1) * TILEB;
        const char* bb = bufB0 + (c & 1) * TILEB;
#pragma unroll
        for (int kk = 0; kk < 2; kk++) {
            int kb = kk * 32 + tg * 4;
            uint32_t cH0 = (uint32_t)((kb     ) ^ mask);
            uint32_t cH1 = (uint32_t)((kb + 16) ^ mask);
            uint32_t cL0 = (uint32_t)((kb + 64) ^ mask);
            uint32_t cL1 = (uint32_t)((kb + 80) ^ mask);
            uint32_t ahi[4][4], alo[4][4], bhi[4][2], blo[4][2];
#pragma unroll
            for (int mt = 0; mt < 4; mt++) {
                int r0 = (wm*64 + mt*16 + g) * 128, r1 = r0 + 1024;
                ahi[mt][0] = *(const uint32_t*)(a + r0 + cH0);
                ahi[mt][1] = *(const uint32_t*)(a + r1 + cH0);
                ahi[mt][2] = *(const uint32_t*)(a + r0 + cH1);
                ahi[mt][3] = *(const uint32_t*)(a + r1 + cH1);
                alo[mt][0] = *(const uint32_t*)(a + r0 + cL0);
                alo[mt][1] = *(const uint32_t*)(a + r1 + cL0);
                alo[mt][2] = *(const uint32_t*)(a + r0 + cL1);
                alo[mt][3] = *(const uint32_t*)(a + r1 + cL1);
            }
#pragma unroll
            for (int nt = 0; nt < 4; nt++) {
                int rn = (wn*32 + nt*8 + g) * 128;
                bhi[nt][0] = *(const uint32_t*)(bb + rn + cH0);
                bhi[nt][1] = *(const uint32_t*)(bb + rn + cH1);
                blo[nt][0] = *(const uint32_t*)(bb + rn + cL0);
                blo[nt][1] = *(const uint32_t*)(bb + rn + cL1);
            }
#pragma unroll
            for (int mt = 0; mt < 4; mt++)
#pragma unroll
                for (int nt = 0; nt < 4; nt++) mma16816(acc[mt][nt], ahi[mt], bhi[nt]);
#pragma unroll
            for (int mt = 0; mt < 4; mt++)
#pragma unroll
                for (int nt = 0; nt < 4; nt++) mma16816(acc[mt][nt], alo[mt], bhi[nt]);
#pragma unroll
            for (int mt = 0; mt < 4; mt++)
#pragma unroll
                for (int nt = 0; nt < 4; nt++) mma16816(acc[mt][nt], ahi[mt], blo[nt]);
        }
        if (c + 1 < nch) {
            stsA((c + 1) & 1, va); stsB((c + 1) & 1, vb);
            __syncthreads();
        }
    }

    // epilogue
#pragma unroll
    for (int mt = 0; mt < 4; mt++) {
        int row = m0 + wm*64 + mt*16 + g;
#pragma unroll
        for (int nt = 0; nt < 4; nt++) {
            int colL = wn*32 + nt*8 + tg*2;
            float c0 = acc[mt][nt][0], c1 = acc[mt][nt][1];
            float c2 = acc[mt][nt][2], c3 = acc[mt][nt][3];
            if (EP == 1) {
                float b0 = sbias[colL], b1 = sbias[colL + 1];
                c0 += b0; c1 += b1; c2 += b0; c3 += b1;
            }
            if (EP == 2) { c0 *= scale; c1 *= scale; c2 *= scale; c3 *= scale; }
            int col = n0 + colL;
            *(float2*)&Cb[(size_t)row * ldc + col]       = make_float2(c0, c1);
            *(float2*)&Cb[(size_t)(row + 8) * ldc + col] = make_float2(c2, c3);
        }
    }
}

// ---------------- GEMM wrappers ----------------
__global__ __launch_bounds__(256, 1) void k_patch(const float* __restrict__ img,
                                                  const float* __restrict__ Wv,
                                                  const float* __restrict__ bv) {
    tc_gemm<1,0,1>(img, Wv, g_patches, CC, HWN, DD, DD,
                   (size_t)CC*HWN, 0, (size_t)HWN*DD, bv, 1.f);
}
__global__ __launch_bounds__(256, 1) void k_tok(const float* __restrict__ txt,
                                                const float* __restrict__ Wt,
                                                const float* __restrict__ bt) {
    tc_gemm<0,0,1>(txt, Wt, g_tokens, DD, DD, DD, DD,
                   (size_t)SS*DD, 0, (size_t)SS*DD, bt, 1.f);
}
__global__ __launch_bounds__(256, 1) void k_sim() {
    tc_gemm<0,0,0>(g_patches, g_tokens, g_sim, DD, DD, DD, SS,
                   (size_t)HWN*DD, (size_t)SS*DD, (size_t)HWN*SS, nullptr, 1.f);
}
__global__ __launch_bounds__(256, 1) void k_lgve() {
    tc_gemm<2,1,0>(g_sim, g_patches, g_lgve, HWN, SS, DD, DD,
                   (size_t)HWN*SS, (size_t)HWN*DD, (size_t)SS*DD, nullptr, 1.f);
}
__global__ __launch_bounds__(256, 1) void k_fsim() {
    tc_gemm<0,0,2>(g_lnv, g_lnt, g_fsim, DD, DD, DD, SS,
                   (size_t)SS*DD, (size_t)SS*DD, (size_t)SS*SS, nullptr, 1.0f/TAUV);
}

// ---------------- column stats: min/max over p, then Z ----------------
__global__ void k_colstats() {
    int b = blockIdx.y;
    int tx = threadIdx.x, ty = threadIdx.y;
    int s = blockIdx.x * 32 + tx;
    const float* simb = g_sim + (size_t)b * HWN * SS;

    __shared__ float red0[8][32], red1[8][32];
    __shared__ float s_mn[32], s_rinv[32];

    float vmn = 1e30f, vmx = -1e30f;
    for (int p = ty; p < HWN; p += 8) {
        float v = simb[(size_t)p * SS + s];
        vmn = fminf(vmn, v);
        vmx = fmaxf(vmx, v);
    }
    red0[ty][tx] = vmn; red1[ty][tx] = vmx;
    __syncthreads();
    if (ty == 0) {
        float mn = red0[0][tx], mx = red1[0][tx];
#pragma unroll
        for (int q = 1; q < 8; q++) {
            mn = fminf(mn, red0[q][tx]);
            mx = fmaxf(mx, red1[q][tx]);
        }
        float rinv = 1.0f / (mx - mn + 1e-8f);
        s_mn[tx] = mn; s_rinv[tx] = rinv;
        g_mn[b*SS + s] = mn;
        g_rinv[b*SS + s] = rinv;
    }
    __syncthreads();
    float mn = s_mn[tx], rinv = s_rinv[tx];
    float zsum = 0.f;
    for (int p = ty; p < HWN; p += 8) {
        float v = simb[(size_t)p * SS + s];
        float tv = (v - mn) * rinv;
        if (tv >= SIGMA) zsum += tv;
    }
    red0[ty][tx] = zsum;
    __syncthreads();
    if (ty == 0) {
        float Z = red0[0][tx];
#pragma unroll
        for (int q = 1; q < 8; q++) Z += red0[q][tx];
        g_zinv[b*SS + s] = 1.0f / fmaxf(Z, 1e-12f);
    }
}

// ---------------- row L2 normalize ----------------
__global__ void k_l2norm(int which) {
    const float* in  = which ? g_tokens : g_lgve;
    float*       out = which ? g_lnt    : g_lnv;
    int warp = threadIdx.x >> 5, lane = threadIdx.x & 31;
    size_t r = (size_t)blockIdx.x * 8 + warp;
    const float* row = in + r * DD;
    float v[8];
    float s = 0.f;
#pragma unroll
    for (int q = 0; q < 8; q++) { v[q] = row[lane + q*32]; s += v[q]*v[q]; }
#pragma unroll
    for (int off = 16; off > 0; off >>= 1) s += __shfl_xor_sync(0xffffffffu, s, off);
    float inv = 1.0f / fmaxf(sqrtf(s), 1e-8f);
#pragma unroll
    for (int q = 0; q < 8; q++) out[r * DD + lane + q*32] = v[q] * inv;
}

// ---------------- mean-pool partials ----------------
__global__ void k_meanp() {
    int ch = blockIdx.x, b = blockIdx.y, d = threadIdx.x;
    const float* base = g_patches + (size_t)b * HWN * DD;
    float s = 0.f;
    for (int p = ch*128; p < ch*128 + 128; p++) s += base[(size_t)p * DD + d];
    g_partV[(b*8 + ch)*DD + d] = s;
}
__global__ void k_meant() {
    int ch = blockIdx.x, b = blockIdx.y, d = threadIdx.x;
    const float* base = g_tokens + (size_t)b * SS * DD;
    float s = 0.f;
    for (int p = ch*128; p < ch*128 + 128; p++) s += base[(size_t)p * DD + d];
    g_partT[(b*4 + ch)*DD + d] = s;
}

// ---------------- global adapters on pooled means ----------------
__global__ void k_gimg(const float* __restrict__ Wv, const float* __restrict__ bv) {
    __shared__ float sm[DD];
    int b = blockIdx.x, d = threadIdx.x;
    float s = 0.f;
#pragma unroll
    for (int ch = 0; ch < 8; ch++) s += g_partV[(b*8 + ch)*DD + d];
    sm[d] = s * (1.0f / (float)HWN);
    __syncthreads();
    const float4* wr = (const float4*)&Wv[(size_t)d * DD];
    float a0 = bv[d], a1 = 0.f, a2 = 0.f, a3 = 0.f;
#pragma unroll
    for (int c = 0; c < DD/4; c++) {
        float4 w = wr[c];
        a0 = fmaf(sm[4*c+0], w.x, a0);
        a1 = fmaf(sm[4*c+1], w.y, a1);
        a2 = fmaf(sm[4*c+2], w.z, a2);
        a3 = fmaf(sm[4*c+3], w.w, a3);
    }
    g_gimg[b*DD + d] = (a0 + a1) + (a2 + a3);
}
__global__ void k_gtxt(const float* __restrict__ Wt, const float* __restrict__ bt) {
    __shared__ float sm[DD];
    int b = blockIdx.x, d = threadIdx.x;
    float s = 0.f;
#pragma unroll
    for (int ch = 0; ch < 4; ch++) s += g_partT[(b*4 + ch)*DD + d];
    sm[d] = s * (1.0f / (float)SS);
    __syncthreads();
    const float4* wr = (const float4*)&Wt[(size_t)d * DD];
    float a0 = bt[d], a1 = 0.f, a2 = 0.f, a3 = 0.f;
#pragma unroll
    for (int c = 0; c < DD/4; c++) {
        float4 w = wr[c];
        a0 = fmaf(sm[4*c+0], w.x, a0);
        a1 = fmaf(sm[4*c+1], w.y, a1);
        a2 = fmaf(sm[4*c+2], w.z, a2);
        a3 = fmaf(sm[4*c+3], w.w, a3);
    }
    g_gtxt[b*DD + d] = (a0 + a1) + (a2 + a3);
}

// ---------------- global embedding norms ----------------
__global__ void k_gnorm() {
    int r = blockIdx.x, lane = threadIdx.x;
    const float* row = (r < 64) ? (g_gimg + (size_t)r * DD)
                                : (g_gtxt + (size_t)(r - 64) * DD);
    float s = 0.f;
#pragma unroll
    for (int q = 0; q < 8; q++) { float v = row[lane + q*32]; s += v*v; }
#pragma unroll
    for (int off = 16; off > 0; off >>= 1) s += __shfl_xor_sync(0xffffffffu, s, off);
    if (lane == 0) g_norms[r] = fmaxf(sqrtf(s), 1e-8f);
}

// ---------------- global sim matrix 64x64 ----------------
__global__ void k_gsim() {
    __shared__ float srow[DD];
    int i = blockIdx.x;
    int warp = threadIdx.x >> 5, lane = threadIdx.x & 31;
    for (int c = threadIdx.x; c < DD; c += 256) srow[c] = g_gimg[(size_t)i * DD + c];
    __syncthreads();
    float ni = g_norms[i];
    for (int j = warp; j < 64; j += 8) {
        const float* trow = g_gtxt + (size_t)j * DD;
        float s = 0.f;
#pragma unroll
        for (int q = 0; q < 8; q++) s += srow[lane + q*32] * trow[lane + q*32];
#pragma unroll
        for (int off = 16; off > 0; off >>= 1) s += __shfl_xor_sync(0xffffffffu, s, off);
        if (lane == 0)
            g_gsim[i*64 + j] = s / (ni * g_norms[64 + j]) * (1.0f / TAUV);
    }
}

// ---------------- global loss ----------------
__global__ void k_gloss() {
    __shared__ float sim[64][65];
    __shared__ float r1[64], r2[64];
    int t = threadIdx.x;  // 64 threads
    for (int idx = t; idx < 4096; idx += 64) sim[idx >> 6][idx & 63] = g_gsim[idx];
    __syncthreads();
    float m = -1e30f;
    for (int j = 0; j < 64; j++) m = fmaxf(m, sim[t][j]);
    float s = 0.f;
    for (int j = 0; j < 64; j++) s += expf(sim[t][j] - m);
    r1[t] = m + logf(s) - sim[t][t];
    m = -1e30f;
    for (int i = 0; i < 64; i++) m = fmaxf(m, sim[i][t]);
    s = 0.f;
    for (int i = 0; i < 64; i++) s += expf(sim[i][t] - m);
    r2[t] = m + logf(s) - sim[t][t];
    __syncthreads();
    if (t == 0) {
        float acc = 0.f;
        for (int r = 0; r < 64; r++) acc += r1[r] + r2[r];
        g_gloss = 0.5f * acc / 64.0f;
    }
}

// ---------------- fsim row / col LSE terms ----------------
__global__ void k_frow() {
    int warp = threadIdx.x >> 5, lane = threadIdx.x & 31;
    int r = blockIdx.x * 8 + warp;
    int b = r >> 9, i = r & (SS - 1);
    const float* row = g_fsim + ((size_t)b * SS + i) * SS;
    float v[16];
#pragma unroll
    for (int q = 0; q < 16; q++) v[q] = row[lane + q*32];
    float m = -1e30f;
#pragma unroll
    for (int q = 0; q < 16; q++) m = fmaxf(m, v[q]);
#pragma unroll
    for (int off = 16; off > 0; off >>= 1) m = fmaxf(m, __shfl_xor_sync(0xffffffffu, m, off));
    float s = 0.f;
#pragma unroll
    for (int q = 0; q < 16; q++) s += expf(v[q] - m);
#pragma unroll
    for (int off = 16; off > 0; off >>= 1) s += __shfl_xor_sync(0xffffffffu, s, off);
    if (lane == 0) g_rowterm[r] = m + logf(s) - row[i];
}

__global__ void k_fcol() {
    int b = blockIdx.y;
    int tx = threadIdx.x, ty = threadIdx.y;
    int j = blockIdx.x * 32 + tx;
    const float* Fb = g_fsim + (size_t)b * SS * SS;
    float m = -1e30f, s = 0.f;
    for (int i = ty; i < SS; i += 8) {
        float x = Fb[(size_t)i * SS + j];
        float nm = fmaxf(m, x);
        s = s * expf(m - nm) + expf(x - nm);
        m = nm;
    }
    __shared__ float sm[8][32], sv[8][32];
    sm[ty][tx] = m; sv[ty][tx] = s;
    __syncthreads();
    if (ty == 0) {
        float M = sm[0][tx], Sv = sv[0][tx];
#pragma unroll
        for (int q = 1; q < 8; q++) {
            float m2 = sm[q][tx], s2 = sv[q][tx];
            float nm = fmaxf(M, m2);
            Sv = Sv * expf(M - nm) + s2 * expf(m2 - nm);
            M = nm;
        }
        g_colterm[b*SS + j] = M + logf(Sv) - Fb[(size_t)j * SS + j];
    }
}

// ---------------- final scalar ----------------
__global__ void k_final(float* out) {
    __shared__ float red[256];
    int t = threadIdx.x;
    float s = 0.f;
    for (int idx = t; idx < BB*SS; idx += 256) s += g_rowterm[idx] + g_colterm[idx];
    red[t] = s;
    __syncthreads();
    for (int o = 128; o > 0; o >>= 1) {
        if (t < o) red[t] += red[t + o];
        __syncthreads();
    }
    if (t == 0) out[0] = g_gloss + 0.5f * red[0] / (float)(BB*SS);
}

// ---------------- launch ----------------
extern "C" void kernel_launch(void* const* d_in, const int* in_sizes, int n_in,
                              void* d_out, int out_size) {
    const float* img = (const float*)d_in[0];
    const float* txt = (const float*)d_in[1];
    const float* Wv  = (const float*)d_in[2];
    const float* bv  = (const float*)d_in[3];
    const float* Wt  = (const float*)d_in[4];
    const float* bt  = (const float*)d_in[5];
    float* out = (float*)d_out;

    static int attr_done = 0;
    if (!attr_done) {
        cudaFuncSetAttribute(k_patch, cudaFuncAttributeMaxDynamicSharedMemorySize, SMEMSZ);
        cudaFuncSetAttribute(k_tok,   cudaFuncAttributeMaxDynamicSharedMemorySize, SMEMSZ);
        cudaFuncSetAttribute(k_sim,   cudaFuncAttributeMaxDynamicSharedMemorySize, SMEMSZ);
        cudaFuncSetAttribute(k_lgve,  cudaFuncAttributeMaxDynamicSharedMemorySize, SMEMSZ);
        cudaFuncSetAttribute(k_fsim,  cudaFuncAttributeMaxDynamicSharedMemorySize, SMEMSZ);
        attr_done = 1;
    }

    k_patch<<<dim3(8, 2, BB), 256, SMEMSZ>>>(img, Wv, bv);   // 1
    k_tok  <<<dim3(4, 2, BB), 256, SMEMSZ>>>(txt, Wt, bt);   // 2
    k_meanp<<<dim3(8, BB), 256>>>();                         // 3
    k_meant<<<dim3(4, BB), 256>>>();                         // 4
    k_gimg <<<BB, 256>>>(Wv, bv);                            // 5
    k_sim  <<<dim3(8, 4, BB), 256, SMEMSZ>>>();              // 6  <- ncu target
    k_gtxt <<<BB, 256>>>(Wt, bt);                            // 7
    k_gnorm<<<128, 32>>>();                                  // 8
    k_gsim <<<64, 256>>>();                                  // 9
    k_gloss<<<1, 64>>>();                                    // 10

    k_colstats<<<dim3(SS/32, BB), dim3(32, 8)>>>();
    k_lgve <<<dim3(4, 2, BB), 256, SMEMSZ>>>();
    k_l2norm<<<(BB*SS)/8, 256>>>(0);  // lgve -> lnv
    k_l2norm<<<(BB*SS)/8, 256>>>(1);  // tokens -> lnt
    k_fsim <<<dim3(4, 4, BB), 256, SMEMSZ>>>();
    k_frow <<<(BB*SS)/8, 256>>>();
    k_fcol <<<dim3(SS/32, BB), dim3(32, 8)>>>();
    k_final<<<1, 256>>>(out);
}